// round 1
// baseline (speedup 1.0000x reference)
#include <cuda_runtime.h>
#include <cuda_bf16.h>
#include <math.h>

// GLIF recurrence, T=4, folded into registers per element.
// x: (B=16, PLANE=2048, L=1024) fp32; params per channel; conduct (T, PLANE).
// out: final spike map o, same shape as x, fp32 in {0,1}.

#define GLIF_T     4
#define GLIF_PLANE 2048
#define GLIF_L     1024

__device__ __forceinline__ float sigmoidf_(float v) {
    return 1.0f / (1.0f + expf(-v));
}

__global__ void __launch_bounds__(256, 8) glif_kernel(
    const float* __restrict__ x,
    const float* __restrict__ alpha,
    const float* __restrict__ beta,
    const float* __restrict__ gamma,
    const float* __restrict__ tau,
    const float* __restrict__ Vth,
    const float* __restrict__ leak,
    const float* __restrict__ reVth,
    const float* __restrict__ conduct,
    float* __restrict__ out)
{
    const int row = blockIdx.x;                 // row = b*PLANE + c
    const int c   = row & (GLIF_PLANE - 1);

    // Per-channel parameters (broadcast loads — all threads in block hit same lines)
    const float al = (alpha[c] > 0.0f) ? 1.0f : 0.0f;   // arch_act(sigmoid(a)) == (a > 0)
    const float be = (beta[c]  > 0.0f) ? 1.0f : 0.0f;
    const float ga = (gamma[c] > 0.0f) ? 1.0f : 0.0f;

    const float tau_s   = sigmoidf_(tau[c]);
    const float vth_s   = sigmoidf_(Vth[c]);
    const float leak_s  = sigmoidf_(leak[c]);
    const float reVth_s = sigmoidf_(reVth[c]);

    const float A  = 1.0f - al * (1.0f - tau_s);
    const float Lk = (1.0f - al) * leak_s;
    const float R  = (1.0f - ga) * reVth_s;

    float s[GLIF_T];
#pragma unroll
    for (int t = 0; t < GLIF_T; ++t) {
        const float ct = sigmoidf_(conduct[t * GLIF_PLANE + c]);
        s[t] = 1.0f - be * (1.0f - ct);
    }

    const size_t base = (size_t)row * GLIF_L;
    const float4 xv = reinterpret_cast<const float4*>(x + base)[threadIdx.x];

    float xl[4] = {xv.x, xv.y, xv.z, xv.w};
    float ov[4];

#pragma unroll
    for (int j = 0; j < 4; ++j) {
        float u = 0.0f, o = 0.0f;
#pragma unroll
        for (int t = 0; t < GLIF_T; ++t) {
            const float I  = xl[j] * s[t];
            // match JAX left-to-right:
            // u_new = A*u*(1-ga*o) - Lk + I - R*o
            float un = A * u * (1.0f - ga * o);
            un = un - Lk;
            un = un + I;
            un = un - R * o;
            o = (un - vth_s > 0.0f) ? 1.0f : 0.0f;
            u = un;
        }
        ov[j] = o;
    }

    float4 res;
    res.x = ov[0]; res.y = ov[1]; res.z = ov[2]; res.w = ov[3];
    reinterpret_cast<float4*>(out + base)[threadIdx.x] = res;
}

extern "C" void kernel_launch(void* const* d_in, const int* in_sizes, int n_in,
                              void* d_out, int out_size) {
    const float* x       = (const float*)d_in[0];
    const float* alpha   = (const float*)d_in[1];
    const float* beta    = (const float*)d_in[2];
    const float* gamma   = (const float*)d_in[3];
    const float* tau     = (const float*)d_in[4];
    const float* Vth     = (const float*)d_in[5];
    const float* leak    = (const float*)d_in[6];
    const float* reVth   = (const float*)d_in[7];
    const float* conduct = (const float*)d_in[8];
    float* out = (float*)d_out;

    const int rows = out_size / GLIF_L;   // B * PLANE = 32768
    glif_kernel<<<rows, 256>>>(x, alpha, beta, gamma, tau, Vth, leak, reVth,
                               conduct, out);
}

// round 2
// speedup vs baseline: 1.7933x; 1.7933x over previous
#include <cuda_runtime.h>
#include <cuda_bf16.h>
#include <math.h>

// GLIF recurrence, T=4. Two-kernel plan:
//   1) glif_params_kernel: per-channel constants (2048 ch) -> __device__ global
//   2) glif_main_kernel: pure streaming recurrence, no transcendentals
//
// x: (B=16, PLANE=2048, L=1024) fp32. out: final spike map, fp32 {0,1}.

#define GLIF_T     4
#define GLIF_PLANE 2048
#define GLIF_L     1024

// Per-channel constants, padded to 48B (3 x float4) for vector broadcast loads.
struct __align__(16) ChParams {
    float A;      // 1 - al*(1 - sigmoid(tau))
    float omg;    // 1 - ga   (extra decay factor applied when o==1)
    float negLk;  // -(1 - al) * sigmoid(leak)
    float negR;   // -(1 - ga) * sigmoid(reVth)
    float vth;    // sigmoid(Vth)
    float s0, s1, s2;   // s_t = 1 - be*(1 - sigmoid(conduct[t,c]))
    float s3;
    float pad0, pad1, pad2;
};

__device__ ChParams g_chp[GLIF_PLANE];

__device__ __forceinline__ float sigmoidf_(float v) {
    return 1.0f / (1.0f + expf(-v));
}

__global__ void glif_params_kernel(
    const float* __restrict__ alpha,
    const float* __restrict__ beta,
    const float* __restrict__ gamma,
    const float* __restrict__ tau,
    const float* __restrict__ Vth,
    const float* __restrict__ leak,
    const float* __restrict__ reVth,
    const float* __restrict__ conduct)
{
    const int c = blockIdx.x * blockDim.x + threadIdx.x;
    if (c >= GLIF_PLANE) return;

    const float al = (alpha[c] > 0.0f) ? 1.0f : 0.0f;   // arch_act(sigmoid(a)) == (a > 0)
    const float be = (beta[c]  > 0.0f) ? 1.0f : 0.0f;
    const float ga = (gamma[c] > 0.0f) ? 1.0f : 0.0f;

    const float tau_s   = sigmoidf_(tau[c]);
    const float vth_s   = sigmoidf_(Vth[c]);
    const float leak_s  = sigmoidf_(leak[c]);
    const float reVth_s = sigmoidf_(reVth[c]);

    ChParams p;
    p.A     = 1.0f - al * (1.0f - tau_s);
    p.omg   = 1.0f - ga;
    p.negLk = -((1.0f - al) * leak_s);
    p.negR  = -((1.0f - ga) * reVth_s);
    p.vth   = vth_s;

    float s[GLIF_T];
#pragma unroll
    for (int t = 0; t < GLIF_T; ++t) {
        const float ct = sigmoidf_(conduct[t * GLIF_PLANE + c]);
        s[t] = 1.0f - be * (1.0f - ct);
    }
    p.s0 = s[0]; p.s1 = s[1]; p.s2 = s[2]; p.s3 = s[3];
    p.pad0 = p.pad1 = p.pad2 = 0.0f;

    g_chp[c] = p;
}

__global__ void __launch_bounds__(256, 8) glif_main_kernel(
    const float* __restrict__ x,
    float* __restrict__ out)
{
    const int row = blockIdx.x;                 // row = b*PLANE + c
    const int c   = row & (GLIF_PLANE - 1);

    // Broadcast load of per-channel constants (all threads same address -> L1 hit)
    const float4* pv = reinterpret_cast<const float4*>(&g_chp[c]);
    const float4 p0 = pv[0];
    const float4 p1 = pv[1];
    const float A = p0.x, omg = p0.y, negLk = p0.z, negR = p0.w;
    const float vth = p1.x;
    const float s0 = p1.y, s1 = p1.z, s2 = p1.w;
    const float s3 = reinterpret_cast<const float*>(&g_chp[c])[8];

    const size_t base = (size_t)row * GLIF_L;
    const float4 xv = reinterpret_cast<const float4*>(x + base)[threadIdx.x];

    float xl[4] = {xv.x, xv.y, xv.z, xv.w};
    float sv[3] = {s1, s2, s3};
    float ov[4];

#pragma unroll
    for (int j = 0; j < 4; ++j) {
        const float xj = xl[j];
        // t = 0: u=0, o=0  ->  u1 = x*s0 - Lk
        float u = fmaf(xj, s0, negLk);
        bool  o = (u > vth);
#pragma unroll
        for (int t = 0; t < 3; ++t) {
            // reference order: ((A*u)*(1-ga*o) - Lk) + x*s - R*o
            const float g = o ? omg : 1.0f;
            float m = (A * u) * g;
            m = m + negLk;
            m = fmaf(xj, sv[t], m);
            if (o) m = m + negR;
            o = (m > vth);
            u = m;
        }
        ov[j] = o ? 1.0f : 0.0f;
    }

    float4 res;
    res.x = ov[0]; res.y = ov[1]; res.z = ov[2]; res.w = ov[3];
    reinterpret_cast<float4*>(out + base)[threadIdx.x] = res;
}

extern "C" void kernel_launch(void* const* d_in, const int* in_sizes, int n_in,
                              void* d_out, int out_size) {
    const float* x       = (const float*)d_in[0];
    const float* alpha   = (const float*)d_in[1];
    const float* beta    = (const float*)d_in[2];
    const float* gamma   = (const float*)d_in[3];
    const float* tau     = (const float*)d_in[4];
    const float* Vth     = (const float*)d_in[5];
    const float* leak    = (const float*)d_in[6];
    const float* reVth   = (const float*)d_in[7];
    const float* conduct = (const float*)d_in[8];
    float* out = (float*)d_out;

    glif_params_kernel<<<(GLIF_PLANE + 255) / 256, 256>>>(
        alpha, beta, gamma, tau, Vth, leak, reVth, conduct);

    const int rows = out_size / GLIF_L;   // B * PLANE = 32768
    glif_main_kernel<<<rows, 256>>>(x, out);
}